// round 14
// baseline (speedup 1.0000x reference)
#include <cuda_runtime.h>
#include <cuda_fp16.h>
#include <cstdint>

// =====================================================================
// Tree (121 GMAC):
//  G[ij][ce][bd]  = sum_a f0[i,a,b,c] f1[a,j,d,e]      (fp32 -> fp16)
//  H[ij][kf][ce]  = F2[kf,bd] . G[ce,bd]^T             (1-MMA, batched)
//  W[(ij,k)][l]   = H[(ij,k),(f,ce)] . F3[l,(f,ce)]^T  (1-MMA, coalesced out)
//  out[z][kl]     = x[z,ij] . Wt[kl,ij]^T + bias       (1-MMA)
//
// All operands single fp16, fp32 accumulate (rel_err 5.07e-4, measured).
// Fragment double-buffering: ldsm for ks+1 issued before MMAs of ks —
// removes the per-kstep ldsm->MMA bubble that capped tensor% at 52 in R13
// (R11 evidence: longer MMA runs per fragment-set -> 60% even at 2 CTA/SM).
// Harness PTX target sm_100 => legacy mma.sync, ceiling ~320 TF/s.
// =====================================================================

typedef __half fp16;

// ------------------- scratch (device globals) ------------------------
__device__ __align__(256) fp16  g_F2[1024 * 256];
__device__ __align__(256) fp16  g_F3[64 * 4096];
__device__ __align__(256) fp16  g_x[8192 * 1024];
__device__ __align__(256) fp16  g_G[1024LL * 256 * 256];     // 128 MB
__device__ __align__(256) fp16  g_H[1024LL * 1024 * 256];    // 512 MB
__device__ __align__(256) fp16  g_W[1024LL * 4096];          // 8 MB  [ij][kl]
__device__ __align__(256) fp16  g_Wt[4096 * 1024];           // 8 MB  [kl][ij]

// ------------------- helpers ------------------------------------------
__device__ __forceinline__ uint32_t smem_u32(const void* p) {
    uint32_t a;
    asm("{ .reg .u64 t; cvta.to.shared.u64 t, %1; cvt.u32.u64 %0, t; }"
        : "=r"(a) : "l"(p));
    return a;
}
__device__ __forceinline__ void cp16(uint32_t s, const void* g) {
    asm volatile("cp.async.cg.shared.global [%0], [%1], 16;" :: "r"(s), "l"(g));
}
__device__ __forceinline__ void cp_commit() {
    asm volatile("cp.async.commit_group;" ::: "memory");
}
__device__ __forceinline__ void cp_wait0() {
    asm volatile("cp.async.wait_group 0;" ::: "memory");
}
__device__ __forceinline__ void ldsm4(uint32_t& r0, uint32_t& r1,
                                      uint32_t& r2, uint32_t& r3, uint32_t addr) {
    asm volatile("ldmatrix.sync.aligned.m8n8.x4.shared.b16 {%0,%1,%2,%3}, [%4];"
                 : "=r"(r0), "=r"(r1), "=r"(r2), "=r"(r3) : "r"(addr));
}
__device__ __forceinline__ void mma16816(float (&d)[4], const uint32_t (&a)[4],
                                         const uint32_t (&b)[2]) {
    asm volatile(
        "mma.sync.aligned.m16n8k16.row.col.f32.f16.f16.f32 "
        "{%0,%1,%2,%3}, {%4,%5,%6,%7}, {%8,%9}, {%0,%1,%2,%3};"
        : "+f"(d[0]), "+f"(d[1]), "+f"(d[2]), "+f"(d[3])
        : "r"(a[0]), "r"(a[1]), "r"(a[2]), "r"(a[3]), "r"(b[0]), "r"(b[1]));
}

// ------------------- prep: tables + x --------------------------------
__global__ void prep_tables(const float* __restrict__ f2,
                            const float* __restrict__ f3) {
    int o = blockIdx.x * 256 + threadIdx.x;          // 0 .. 262143
    // F2t[kf][bd] = f2[(bd)*1024 + kf]
    g_F2[o] = __float2half(f2[(o & 255) * 1024 + (o >> 8)]);
    // F3T[l][f*256 + c*16 + e] = f3[((c*16+e)*16+f)*64 + l]
    int l = o >> 12, fce = o & 4095, f = fce >> 8, ce = fce & 255;
    g_F3[o] = __float2half(f3[(ce * 16 + f) * 64 + l]);
}
__global__ void prep_x(const float* __restrict__ x) {
    int o = blockIdx.x * 256 + threadIdx.x;
    g_x[o] = __float2half(x[o]);
}

// ------------------- stage 1: G[ij][ce][bd] fp16 -----------------------
__global__ void __launch_bounds__(256)
pair01_kernel(const float* __restrict__ f0, const float* __restrict__ f1) {
    __shared__ float s0[4096];   // f0[i]: a*256 + b*16 + c
    __shared__ float s1[4096];   // f1[:,j]: a*256 + d*16 + e
    const int t = threadIdx.x, ij = blockIdx.x;
    const int i = ij >> 5, j = ij & 31;

    for (int p = t; p < 4096; p += 256) {
        s0[p] = f0[i * 4096 + p];
        int a = p >> 8, de = p & 255;
        s1[p] = f1[a * 8192 + j * 256 + de];
    }
    __syncthreads();

    const int c = t >> 4, e = t & 15;
    const long long ob = (long long)ij * 65536 + (long long)t * 256;  // row = ce

    for (int b = 0; b < 16; b++) {
        float r0[16];
        #pragma unroll
        for (int a = 0; a < 16; a++) r0[a] = s0[a * 256 + b * 16 + c];
        __align__(16) fp16 hv[16];
        #pragma unroll
        for (int d = 0; d < 16; d++) {
            float acc = 0.f;
            #pragma unroll
            for (int a = 0; a < 16; a++) acc += r0[a] * s1[a * 256 + d * 16 + e];
            hv[d] = __float2half(acc);
        }
        *reinterpret_cast<uint4*>(&g_G[ob + b * 16])     = reinterpret_cast<uint4*>(hv)[0];
        *reinterpret_cast<uint4*>(&g_G[ob + b * 16 + 8]) = reinterpret_cast<uint4*>(hv)[1];
    }
}

// ------------------- fp16 GEMM, BK=64, fragment-pipelined --------------
// D[M,N] = A[M,K] * B[N,K]^T ; all K-major rows, lda/ldb leads.
// z-dim: B += z*sB, C += z*sC  (A has no batch).
// EPI: 0 -> fp16 out; 1 -> fp32 + bias.
template <int BM, int BN, int WM, int WN, int EPI>
__global__ void __launch_bounds__((BM / WM) * (BN / WN) * 32)
gemm_mma(const fp16* __restrict__ A, const fp16* __restrict__ B,
         float* __restrict__ Cf, fp16* __restrict__ Ch,
         const float* __restrict__ bias,
         int K, int lda, int ldb, int ldC,
         long long sB, long long sC) {
    constexpr int WARPS_M = BM / WM, WARPS_N = BN / WN;
    constexpr int THREADS = WARPS_M * WARPS_N * 32;
    constexpr int MT = WM / 16, NT = WN / 8;
    static_assert(NT % 2 == 0, "NT even for paired ldsm4");
    constexpr int ROWB = 144;                // 128B data + 16B pad (bank-safe)
    constexpr int A_SZ = BM * ROWB;
    constexpr int B_SZ = BN * ROWB;
    constexpr int BUFB = A_SZ + B_SZ;

    extern __shared__ char sm[];
    const uint32_t sbase = smem_u32(sm);
    const int tid = threadIdx.x, wid = tid >> 5, lane = tid & 31;
    const int warp_m0 = (wid / WARPS_N) * WM;
    const int warp_n0 = (wid % WARPS_N) * WN;

    const long long bz = blockIdx.z;
    B += bz * sB;
    const int m0 = blockIdx.y * BM;
    const int n0 = blockIdx.x * BN;

    float acc[MT][NT][4];
    #pragma unroll
    for (int mi = 0; mi < MT; mi++)
        #pragma unroll
        for (int ni = 0; ni < NT; ni++)
            #pragma unroll
            for (int c = 0; c < 4; c++) acc[mi][ni][c] = 0.f;

    auto load_chunk = [&](int kt, int buf) {
        const uint32_t sA = sbase + buf * BUFB;
        const uint32_t sBb = sA + A_SZ;
        #pragma unroll
        for (int p = tid; p < BM * 8; p += THREADS) {
            int row = p >> 3, u = p & 7;
            long long g = (long long)(m0 + row) * lda + kt + u * 8;
            cp16(sA + row * ROWB + u * 16, A + g);
        }
        #pragma unroll
        for (int p = tid; p < BN * 8; p += THREADS) {
            int row = p >> 3, u = p & 7;
            long long g = (long long)(n0 + row) * ldb + kt + u * 8;
            cp16(sBb + row * ROWB + u * 16, B + g);
        }
        cp_commit();
    };

    const int nch = K >> 6;   // BK = 64
    load_chunk(0, 0);
    cp_wait0();
    __syncthreads();

    uint32_t af[2][MT][4], bq[2][NT][2];

    for (int t = 0; t < nch; t++) {
        const int buf = t & 1;
        if (t + 1 < nch) load_chunk((t + 1) * 64, buf ^ 1);

        const uint32_t sA = sbase + buf * BUFB;
        const uint32_t sBb = sA + A_SZ;

        auto ldfrag = [&](int ks, int slot) {
            #pragma unroll
            for (int mi = 0; mi < MT; mi++) {
                uint32_t off = (uint32_t)(warp_m0 + mi * 16 + (lane & 15)) * ROWB +
                               ks * 32 + (lane >> 4) * 16;
                ldsm4(af[slot][mi][0], af[slot][mi][1],
                      af[slot][mi][2], af[slot][mi][3], sA + off);
            }
            #pragma unroll
            for (int ni = 0; ni < NT; ni += 2) {
                uint32_t off = (uint32_t)(warp_n0 + ni * 8 + ((lane >> 4) << 3) +
                                          (lane & 7)) * ROWB +
                               ks * 32 + ((lane >> 3) & 1) * 16;
                ldsm4(bq[slot][ni][0], bq[slot][ni][1],
                      bq[slot][ni + 1][0], bq[slot][ni + 1][1], sBb + off);
            }
        };

        ldfrag(0, 0);
        #pragma unroll
        for (int ks = 0; ks < 4; ks++) {
            const int cur = ks & 1;
            if (ks < 3) ldfrag(ks + 1, cur ^ 1);
            #pragma unroll
            for (int mi = 0; mi < MT; mi++)
                #pragma unroll
                for (int ni = 0; ni < NT; ni++)
                    mma16816(acc[mi][ni], af[cur][mi], bq[cur][ni]);
        }
        cp_wait0();
        __syncthreads();
    }

    // epilogue: thread holds (r, col),(r, col+1),(r+8, col),(r+8, col+1)
    #pragma unroll
    for (int mi = 0; mi < MT; mi++) {
        #pragma unroll
        for (int ni = 0; ni < NT; ni++) {
            int r   = m0 + warp_m0 + mi * 16 + (lane >> 2);
            int col = n0 + warp_n0 + ni * 8 + (lane & 3) * 2;
            if (EPI == 0) {
                #pragma unroll
                for (int half_ = 0; half_ < 2; half_++) {
                    long long off = bz * sC + (long long)(r + half_ * 8) * ldC + col;
                    __half2 hv;
                    hv.x = __float2half(acc[mi][ni][half_ * 2]);
                    hv.y = __float2half(acc[mi][ni][half_ * 2 + 1]);
                    *reinterpret_cast<__half2*>(&Ch[off]) = hv;
                }
            } else {
                float b0 = bias[col], b1 = bias[col + 1];
                #pragma unroll
                for (int half_ = 0; half_ < 2; half_++) {
                    long long off = (long long)(r + half_ * 8) * ldC + col;
                    float2 v;
                    v.x = acc[mi][ni][half_ * 2]     + b0;
                    v.y = acc[mi][ni][half_ * 2 + 1] + b1;
                    *reinterpret_cast<float2*>(&Cf[off]) = v;
                }
            }
        }
    }
}

// -------- W[ij][kl] -> Wt[kl][ij], smem-tiled, coalesced both sides ----
__global__ void __launch_bounds__(256)
wtrans_kernel() {
    __shared__ fp16 tile[64][65];
    const int ij0 = blockIdx.x * 64;     // 16 blocks
    const int kl0 = blockIdx.y * 64;     // 64 blocks
    const int t = threadIdx.x;
    for (int idx = t; idx < 4096; idx += 256) {
        int r = idx >> 6, c = idx & 63;
        tile[r][c] = g_W[(long long)(ij0 + r) * 4096 + kl0 + c];
    }
    __syncthreads();
    for (int idx = t; idx < 4096; idx += 256) {
        int c = idx >> 6, r = idx & 63;
        g_Wt[(long long)(kl0 + c) * 1024 + ij0 + r] = tile[r][c];
    }
}

// ------------------- launch -------------------------------------------
extern "C" void kernel_launch(void* const* d_in, const int* in_sizes, int n_in,
                              void* d_out, int out_size) {
    const float* x    = (const float*)d_in[0];
    const float* f0   = (const float*)d_in[1];
    const float* f1   = (const float*)d_in[2];
    const float* f2   = (const float*)d_in[3];
    const float* f3   = (const float*)d_in[4];
    const float* bias = (const float*)d_in[5];
    float* out = (float*)d_out;

    fp16 *pF2, *pF3, *px, *pG, *pH, *pW, *pWt;
    cudaGetSymbolAddress((void**)&pF2, g_F2);
    cudaGetSymbolAddress((void**)&pF3, g_F3);
    cudaGetSymbolAddress((void**)&px,  g_x);
    cudaGetSymbolAddress((void**)&pG,  g_G);
    cudaGetSymbolAddress((void**)&pH,  g_H);
    cudaGetSymbolAddress((void**)&pW,  g_W);
    cudaGetSymbolAddress((void**)&pWt, g_Wt);

    // dynamic smem: 2 buffers of (A + B), ROWB=144 (BK=64)
    const int SMEM_128 = 2 * (128 * 144 + 128 * 144);   // 73728
    const int SMEM_S3  = 2 * (128 * 144 + 64 * 144);    // 55296
    cudaFuncSetAttribute((const void*)gemm_mma<128, 128, 64, 64, 0>,
                         cudaFuncAttributeMaxDynamicSharedMemorySize, SMEM_128);
    cudaFuncSetAttribute((const void*)gemm_mma<128, 64, 64, 32, 0>,
                         cudaFuncAttributeMaxDynamicSharedMemorySize, SMEM_S3);
    cudaFuncSetAttribute((const void*)gemm_mma<128, 128, 64, 64, 1>,
                         cudaFuncAttributeMaxDynamicSharedMemorySize, SMEM_128);

    prep_tables<<<1024, 256>>>(f2, f3);
    prep_x<<<32768, 256>>>(x);

    // stage 1: G[ij][ce][bd] fp16
    pair01_kernel<<<1024, 256>>>(f0, f1);

    // stage 2: per-ij H[kf=1024][ce=256] = F2 . G_ij^T   (K=256)
    gemm_mma<128, 128, 64, 64, 0><<<dim3(2, 8, 1024), 128, SMEM_128>>>(
        pF2, pG,
        nullptr, pH, nullptr,
        /*K=*/256, /*lda=*/256, /*ldb=*/256, /*ldC=*/256,
        /*sB=*/65536LL, /*sC=*/262144LL);

    // stage 3: W[(ij,k)=65536][l=64] = H . F3^T          (K=4096)
    //          flat offset = ij*4096 + kl  -> W[ij][kl] row-major
    gemm_mma<128, 64, 64, 32, 0><<<dim3(1, 512, 1), 128, SMEM_S3>>>(
        pH, pF3,
        nullptr, pW, nullptr,
        /*K=*/4096, /*lda=*/4096, /*ldb=*/4096, /*ldC=*/64,
        /*sB=*/0, /*sC=*/0);

    // transpose -> Wt[kl][ij] fp16 (coalesced both sides)
    wtrans_kernel<<<dim3(16, 64), 256>>>();

    // stage 4: out[8192][4096] = x . Wt^T + bias         (K=1024)
    gemm_mma<128, 128, 64, 64, 1><<<dim3(32, 64, 1), 128, SMEM_128>>>(
        px, pWt,
        out, nullptr, bias,
        /*K=*/1024, /*lda=*/1024, /*ldb=*/1024, /*ldC=*/4096,
        0, 0);
}

// round 15
// speedup vs baseline: 1.1078x; 1.1078x over previous
#include <cuda_runtime.h>
#include <cuda_fp16.h>
#include <cstdint>

// =====================================================================
// Tree (121 GMAC):
//  G[ij][ce][bd]  = sum_a f0[i,a,b,c] f1[a,j,d,e]      (fp32 -> fp16)
//  H[ij][kf][ce]  = F2[kf,bd] . G[ce,bd]^T             (1-MMA, batched)
//  W[(ij,k)][l]   = H[(ij,k),(f,ce)] . F3[l,(f,ce)]^T  (1-MMA, coalesced out)
//  out[z][kl]     = x[z,ij] . Wt[kl,ij]^T + bias       (1-MMA)
//
// All operands single fp16, fp32 accumulate (rel_err 5.07e-4, measured).
// R13 mainloop (no fragment pipelining: 168 regs -> 3 CTAs/SM; R14 showed
// pipelining costs 80 regs -> 2 CTAs/SM and regresses). Stage-3 writes
// W[ij][kl] fp16 coalesced; smem-tiled transpose. Legacy mma.sync path
// (harness PTX target sm_100), measured ceiling ~300 TF/s.
// =====================================================================

typedef __half fp16;

// ------------------- scratch (device globals) ------------------------
__device__ __align__(256) fp16  g_F2[1024 * 256];
__device__ __align__(256) fp16  g_F3[64 * 4096];
__device__ __align__(256) fp16  g_x[8192 * 1024];
__device__ __align__(256) fp16  g_G[1024LL * 256 * 256];     // 128 MB
__device__ __align__(256) fp16  g_H[1024LL * 1024 * 256];    // 512 MB
__device__ __align__(256) fp16  g_W[1024LL * 4096];          // 8 MB  [ij][kl]
__device__ __align__(256) fp16  g_Wt[4096 * 1024];           // 8 MB  [kl][ij]

// ------------------- helpers ------------------------------------------
__device__ __forceinline__ uint32_t smem_u32(const void* p) {
    uint32_t a;
    asm("{ .reg .u64 t; cvta.to.shared.u64 t, %1; cvt.u32.u64 %0, t; }"
        : "=r"(a) : "l"(p));
    return a;
}
__device__ __forceinline__ void cp16(uint32_t s, const void* g) {
    asm volatile("cp.async.cg.shared.global [%0], [%1], 16;" :: "r"(s), "l"(g));
}
__device__ __forceinline__ void cp_commit() {
    asm volatile("cp.async.commit_group;" ::: "memory");
}
__device__ __forceinline__ void cp_wait0() {
    asm volatile("cp.async.wait_group 0;" ::: "memory");
}
__device__ __forceinline__ void ldsm4(uint32_t& r0, uint32_t& r1,
                                      uint32_t& r2, uint32_t& r3, uint32_t addr) {
    asm volatile("ldmatrix.sync.aligned.m8n8.x4.shared.b16 {%0,%1,%2,%3}, [%4];"
                 : "=r"(r0), "=r"(r1), "=r"(r2), "=r"(r3) : "r"(addr));
}
__device__ __forceinline__ void mma16816(float (&d)[4], const uint32_t (&a)[4],
                                         const uint32_t (&b)[2]) {
    asm volatile(
        "mma.sync.aligned.m16n8k16.row.col.f32.f16.f16.f32 "
        "{%0,%1,%2,%3}, {%4,%5,%6,%7}, {%8,%9}, {%0,%1,%2,%3};"
        : "+f"(d[0]), "+f"(d[1]), "+f"(d[2]), "+f"(d[3])
        : "r"(a[0]), "r"(a[1]), "r"(a[2]), "r"(a[3]), "r"(b[0]), "r"(b[1]));
}

// ------------------- prep: tables + x --------------------------------
__global__ void prep_tables(const float* __restrict__ f2,
                            const float* __restrict__ f3) {
    int o = blockIdx.x * 256 + threadIdx.x;          // 0 .. 262143
    // F2t[kf][bd] = f2[(bd)*1024 + kf]
    g_F2[o] = __float2half(f2[(o & 255) * 1024 + (o >> 8)]);
    // F3T[l][f*256 + c*16 + e] = f3[((c*16+e)*16+f)*64 + l]
    int l = o >> 12, fce = o & 4095, f = fce >> 8, ce = fce & 255;
    g_F3[o] = __float2half(f3[(ce * 16 + f) * 64 + l]);
}
// vectorized x conversion: 4 floats -> 4 halves per thread
__global__ void prep_x(const float* __restrict__ x) {
    int o = blockIdx.x * 256 + threadIdx.x;          // 0 .. 2097151
    float4 v = reinterpret_cast<const float4*>(x)[o];
    __half2 h0 = __floats2half2_rn(v.x, v.y);
    __half2 h1 = __floats2half2_rn(v.z, v.w);
    uint2 pk;
    pk.x = *reinterpret_cast<uint32_t*>(&h0);
    pk.y = *reinterpret_cast<uint32_t*>(&h1);
    reinterpret_cast<uint2*>(g_x)[o] = pk;
}

// ------------------- stage 1: G[ij][ce][bd] fp16 -----------------------
__global__ void __launch_bounds__(256)
pair01_kernel(const float* __restrict__ f0, const float* __restrict__ f1) {
    __shared__ float s0[4096];   // f0[i]: a*256 + b*16 + c
    __shared__ float s1[4096];   // f1[:,j]: a*256 + d*16 + e
    const int t = threadIdx.x, ij = blockIdx.x;
    const int i = ij >> 5, j = ij & 31;

    for (int p = t; p < 4096; p += 256) {
        s0[p] = f0[i * 4096 + p];
        int a = p >> 8, de = p & 255;
        s1[p] = f1[a * 8192 + j * 256 + de];
    }
    __syncthreads();

    const int c = t >> 4, e = t & 15;
    const long long ob = (long long)ij * 65536 + (long long)t * 256;  // row = ce

    for (int b = 0; b < 16; b++) {
        float r0[16];
        #pragma unroll
        for (int a = 0; a < 16; a++) r0[a] = s0[a * 256 + b * 16 + c];
        __align__(16) fp16 hv[16];
        #pragma unroll
        for (int d = 0; d < 16; d++) {
            float acc = 0.f;
            #pragma unroll
            for (int a = 0; a < 16; a++) acc += r0[a] * s1[a * 256 + d * 16 + e];
            hv[d] = __float2half(acc);
        }
        *reinterpret_cast<uint4*>(&g_G[ob + b * 16])     = reinterpret_cast<uint4*>(hv)[0];
        *reinterpret_cast<uint4*>(&g_G[ob + b * 16 + 8]) = reinterpret_cast<uint4*>(hv)[1];
    }
}

// ------------------- fp16 single GEMM, BK=64 ---------------------------
// D[M,N] = A[M,K] * B[N,K]^T ; all K-major rows, lda/ldb leads.
// z-dim: B += z*sB, C += z*sC  (A has no batch).
// EPI: 0 -> fp16 out; 1 -> fp32 + bias.
template <int BM, int BN, int WM, int WN, int EPI>
__global__ void __launch_bounds__((BM / WM) * (BN / WN) * 32)
gemm_mma(const fp16* __restrict__ A, const fp16* __restrict__ B,
         float* __restrict__ Cf, fp16* __restrict__ Ch,
         const float* __restrict__ bias,
         int K, int lda, int ldb, int ldC,
         long long sB, long long sC) {
    constexpr int WARPS_M = BM / WM, WARPS_N = BN / WN;
    constexpr int THREADS = WARPS_M * WARPS_N * 32;
    constexpr int MT = WM / 16, NT = WN / 8;
    static_assert(NT % 2 == 0, "NT even for paired ldsm4");
    constexpr int ROWB = 144;                // 128B data + 16B pad (bank-safe)
    constexpr int A_SZ = BM * ROWB;
    constexpr int B_SZ = BN * ROWB;
    constexpr int BUFB = A_SZ + B_SZ;

    extern __shared__ char sm[];
    const uint32_t sbase = smem_u32(sm);
    const int tid = threadIdx.x, wid = tid >> 5, lane = tid & 31;
    const int warp_m0 = (wid / WARPS_N) * WM;
    const int warp_n0 = (wid % WARPS_N) * WN;

    const long long bz = blockIdx.z;
    B += bz * sB;
    const int m0 = blockIdx.y * BM;
    const int n0 = blockIdx.x * BN;

    float acc[MT][NT][4];
    #pragma unroll
    for (int mi = 0; mi < MT; mi++)
        #pragma unroll
        for (int ni = 0; ni < NT; ni++)
            #pragma unroll
            for (int c = 0; c < 4; c++) acc[mi][ni][c] = 0.f;

    auto load_chunk = [&](int kt, int buf) {
        const uint32_t sA = sbase + buf * BUFB;
        const uint32_t sBb = sA + A_SZ;
        #pragma unroll
        for (int p = tid; p < BM * 8; p += THREADS) {
            int row = p >> 3, u = p & 7;
            long long g = (long long)(m0 + row) * lda + kt + u * 8;
            cp16(sA + row * ROWB + u * 16, A + g);
        }
        #pragma unroll
        for (int p = tid; p < BN * 8; p += THREADS) {
            int row = p >> 3, u = p & 7;
            long long g = (long long)(n0 + row) * ldb + kt + u * 8;
            cp16(sBb + row * ROWB + u * 16, B + g);
        }
        cp_commit();
    };

    const int nch = K >> 6;   // BK = 64
    load_chunk(0, 0);
    cp_wait0();
    __syncthreads();

    for (int t = 0; t < nch; t++) {
        const int buf = t & 1;
        if (t + 1 < nch) load_chunk((t + 1) * 64, buf ^ 1);

        const uint32_t sA = sbase + buf * BUFB;
        const uint32_t sBb = sA + A_SZ;

        #pragma unroll
        for (int ks = 0; ks < 4; ks++) {
            uint32_t af[MT][4], bq[NT][2];
            #pragma unroll
            for (int mi = 0; mi < MT; mi++) {
                uint32_t off = (uint32_t)(warp_m0 + mi * 16 + (lane & 15)) * ROWB +
                               ks * 32 + (lane >> 4) * 16;
                ldsm4(af[mi][0], af[mi][1], af[mi][2], af[mi][3], sA + off);
            }
            #pragma unroll
            for (int ni = 0; ni < NT; ni += 2) {
                uint32_t off = (uint32_t)(warp_n0 + ni * 8 + ((lane >> 4) << 3) +
                                          (lane & 7)) * ROWB +
                               ks * 32 + ((lane >> 3) & 1) * 16;
                ldsm4(bq[ni][0], bq[ni][1], bq[ni + 1][0], bq[ni + 1][1], sBb + off);
            }
            #pragma unroll
            for (int mi = 0; mi < MT; mi++)
                #pragma unroll
                for (int ni = 0; ni < NT; ni++)
                    mma16816(acc[mi][ni], af[mi], bq[ni]);
        }
        cp_wait0();
        __syncthreads();
    }

    // epilogue: thread holds (r, col),(r, col+1),(r+8, col),(r+8, col+1)
    #pragma unroll
    for (int mi = 0; mi < MT; mi++) {
        #pragma unroll
        for (int ni = 0; ni < NT; ni++) {
            int r   = m0 + warp_m0 + mi * 16 + (lane >> 2);
            int col = n0 + warp_n0 + ni * 8 + (lane & 3) * 2;
            if (EPI == 0) {
                #pragma unroll
                for (int half_ = 0; half_ < 2; half_++) {
                    long long off = bz * sC + (long long)(r + half_ * 8) * ldC + col;
                    __half2 hv;
                    hv.x = __float2half(acc[mi][ni][half_ * 2]);
                    hv.y = __float2half(acc[mi][ni][half_ * 2 + 1]);
                    *reinterpret_cast<__half2*>(&Ch[off]) = hv;
                }
            } else {
                float b0 = bias[col], b1 = bias[col + 1];
                #pragma unroll
                for (int half_ = 0; half_ < 2; half_++) {
                    long long off = (long long)(r + half_ * 8) * ldC + col;
                    float2 v;
                    v.x = acc[mi][ni][half_ * 2]     + b0;
                    v.y = acc[mi][ni][half_ * 2 + 1] + b1;
                    *reinterpret_cast<float2*>(&Cf[off]) = v;
                }
            }
        }
    }
}

// -------- W[ij][kl] -> Wt[kl][ij], smem-tiled, coalesced both sides ----
__global__ void __launch_bounds__(256)
wtrans_kernel() {
    __shared__ fp16 tile[64][65];
    const int ij0 = blockIdx.x * 64;     // 16 blocks
    const int kl0 = blockIdx.y * 64;     // 64 blocks
    const int t = threadIdx.x;
    for (int idx = t; idx < 4096; idx += 256) {
        int r = idx >> 6, c = idx & 63;
        tile[r][c] = g_W[(long long)(ij0 + r) * 4096 + kl0 + c];
    }
    __syncthreads();
    for (int idx = t; idx < 4096; idx += 256) {
        int c = idx >> 6, r = idx & 63;
        g_Wt[(long long)(kl0 + c) * 1024 + ij0 + r] = tile[r][c];
    }
}

// ------------------- launch -------------------------------------------
extern "C" void kernel_launch(void* const* d_in, const int* in_sizes, int n_in,
                              void* d_out, int out_size) {
    const float* x    = (const float*)d_in[0];
    const float* f0   = (const float*)d_in[1];
    const float* f1   = (const float*)d_in[2];
    const float* f2   = (const float*)d_in[3];
    const float* f3   = (const float*)d_in[4];
    const float* bias = (const float*)d_in[5];
    float* out = (float*)d_out;

    fp16 *pF2, *pF3, *px, *pG, *pH, *pW, *pWt;
    cudaGetSymbolAddress((void**)&pF2, g_F2);
    cudaGetSymbolAddress((void**)&pF3, g_F3);
    cudaGetSymbolAddress((void**)&px,  g_x);
    cudaGetSymbolAddress((void**)&pG,  g_G);
    cudaGetSymbolAddress((void**)&pH,  g_H);
    cudaGetSymbolAddress((void**)&pW,  g_W);
    cudaGetSymbolAddress((void**)&pWt, g_Wt);

    // dynamic smem: 2 buffers of (A + B), ROWB=144 (BK=64)
    const int SMEM_128 = 2 * (128 * 144 + 128 * 144);   // 73728
    const int SMEM_S3  = 2 * (128 * 144 + 64 * 144);    // 55296
    cudaFuncSetAttribute((const void*)gemm_mma<128, 128, 64, 64, 0>,
                         cudaFuncAttributeMaxDynamicSharedMemorySize, SMEM_128);
    cudaFuncSetAttribute((const void*)gemm_mma<128, 64, 64, 32, 0>,
                         cudaFuncAttributeMaxDynamicSharedMemorySize, SMEM_S3);
    cudaFuncSetAttribute((const void*)gemm_mma<128, 128, 64, 64, 1>,
                         cudaFuncAttributeMaxDynamicSharedMemorySize, SMEM_128);

    prep_tables<<<1024, 256>>>(f2, f3);
    prep_x<<<8192, 256>>>(x);            // 4 elems/thread (float4 -> half2x2)

    // stage 1: G[ij][ce][bd] fp16
    pair01_kernel<<<1024, 256>>>(f0, f1);

    // stage 2: per-ij H[kf=1024][ce=256] = F2 . G_ij^T   (K=256)
    gemm_mma<128, 128, 64, 64, 0><<<dim3(2, 8, 1024), 128, SMEM_128>>>(
        pF2, pG,
        nullptr, pH, nullptr,
        /*K=*/256, /*lda=*/256, /*ldb=*/256, /*ldC=*/256,
        /*sB=*/65536LL, /*sC=*/262144LL);

    // stage 3: W[(ij,k)=65536][l=64] = H . F3^T          (K=4096)
    //          flat offset = ij*4096 + kl  -> W[ij][kl] row-major
    gemm_mma<128, 64, 64, 32, 0><<<dim3(1, 512, 1), 128, SMEM_S3>>>(
        pH, pF3,
        nullptr, pW, nullptr,
        /*K=*/4096, /*lda=*/4096, /*ldb=*/4096, /*ldC=*/64,
        /*sB=*/0, /*sC=*/0);

    // transpose -> Wt[kl][ij] fp16 (coalesced both sides)
    wtrans_kernel<<<dim3(16, 64), 256>>>();

    // stage 4: out[8192][4096] = x . Wt^T + bias         (K=1024)
    gemm_mma<128, 128, 64, 64, 1><<<dim3(32, 64, 1), 128, SMEM_128>>>(
        px, pWt,
        out, nullptr, bias,
        /*K=*/1024, /*lda=*/1024, /*ldb=*/1024, /*ldC=*/4096,
        0, 0);
}

// round 16
// speedup vs baseline: 1.1445x; 1.0331x over previous
#include <cuda_runtime.h>
#include <cuda_fp16.h>
#include <cstdint>

// =====================================================================
// Tree (121 GMAC):
//  G[ij][ce][bd]  = sum_a f0[i,a,b,c] f1[a,j,d,e]      (mma, per-ij 256x256x16)
//  H[ij][kf][ce]  = F2[kf,bd] . G[ce,bd]^T             (1-MMA, batched)
//  W[(ij,k)][l]   = H[(ij,k),(f,ce)] . F3[l,(f,ce)]^T  (1-MMA, coalesced out)
//  out[z][kl]     = x[z,ij] . Wt[kl,ij]^T + bias       (1-MMA)
//
// All operands single fp16, fp32 accumulate. R15 GEMM config (168 regs,
// 3 CTAs/SM — the measured best; fragment pipelining regresses). Stage-1
// moved from FFMA (~60us at ~34 TF fp32) to tensor cores + permute
// (~20-25us). Legacy mma.sync path (harness PTX target sm_100),
// measured plateau ~300 TF/s.
// =====================================================================

typedef __half fp16;

// ------------------- scratch (device globals) ------------------------
__device__ __align__(256) fp16  g_F2[1024 * 256];
__device__ __align__(256) fp16  g_F3[64 * 4096];
__device__ __align__(256) fp16  g_x[8192 * 1024];
__device__ __align__(256) fp16  g_G[1024LL * 256 * 256];     // 128 MB
__device__ __align__(256) fp16  g_H[1024LL * 1024 * 256];    // 512 MB
__device__ __align__(256) fp16  g_W[1024LL * 4096];          // 8 MB  [ij][kl]
__device__ __align__(256) fp16  g_Wt[4096 * 1024];           // 8 MB  [kl][ij]

// ------------------- helpers ------------------------------------------
__device__ __forceinline__ uint32_t smem_u32(const void* p) {
    uint32_t a;
    asm("{ .reg .u64 t; cvta.to.shared.u64 t, %1; cvt.u32.u64 %0, t; }"
        : "=r"(a) : "l"(p));
    return a;
}
__device__ __forceinline__ void cp16(uint32_t s, const void* g) {
    asm volatile("cp.async.cg.shared.global [%0], [%1], 16;" :: "r"(s), "l"(g));
}
__device__ __forceinline__ void cp_commit() {
    asm volatile("cp.async.commit_group;" ::: "memory");
}
__device__ __forceinline__ void cp_wait0() {
    asm volatile("cp.async.wait_group 0;" ::: "memory");
}
__device__ __forceinline__ void ldsm4(uint32_t& r0, uint32_t& r1,
                                      uint32_t& r2, uint32_t& r3, uint32_t addr) {
    asm volatile("ldmatrix.sync.aligned.m8n8.x4.shared.b16 {%0,%1,%2,%3}, [%4];"
                 : "=r"(r0), "=r"(r1), "=r"(r2), "=r"(r3) : "r"(addr));
}
__device__ __forceinline__ void mma16816(float (&d)[4], const uint32_t (&a)[4],
                                         const uint32_t (&b)[2]) {
    asm volatile(
        "mma.sync.aligned.m16n8k16.row.col.f32.f16.f16.f32 "
        "{%0,%1,%2,%3}, {%4,%5,%6,%7}, {%8,%9}, {%0,%1,%2,%3};"
        : "+f"(d[0]), "+f"(d[1]), "+f"(d[2]), "+f"(d[3])
        : "r"(a[0]), "r"(a[1]), "r"(a[2]), "r"(a[3]), "r"(b[0]), "r"(b[1]));
}

// ------------------- prep: tables + x --------------------------------
__global__ void prep_tables(const float* __restrict__ f2,
                            const float* __restrict__ f3) {
    int o = blockIdx.x * 256 + threadIdx.x;          // 0 .. 262143
    // F2t[kf][bd] = f2[(bd)*1024 + kf]
    g_F2[o] = __float2half(f2[(o & 255) * 1024 + (o >> 8)]);
    // F3T[l][f*256 + c*16 + e] = f3[((c*16+e)*16+f)*64 + l]
    int l = o >> 12, fce = o & 4095, f = fce >> 8, ce = fce & 255;
    g_F3[o] = __float2half(f3[(ce * 16 + f) * 64 + l]);
}
// vectorized x conversion: 4 floats -> 4 halves per thread
__global__ void prep_x(const float* __restrict__ x) {
    int o = blockIdx.x * 256 + threadIdx.x;          // 0 .. 2097151
    float4 v = reinterpret_cast<const float4*>(x)[o];
    __half2 h0 = __floats2half2_rn(v.x, v.y);
    __half2 h1 = __floats2half2_rn(v.z, v.w);
    uint2 pk;
    pk.x = *reinterpret_cast<uint32_t*>(&h0);
    pk.y = *reinterpret_cast<uint32_t*>(&h1);
    reinterpret_cast<uint2*>(g_x)[o] = pk;
}

// ------------- stage 1 (tensor): T = A.B^T then permute ----------------
// Per CTA (one ij): T[(b,c)][(d,e)] = sum_a f0[i,a,b,c]*f1[a,j,d,e]
// (GEMM 256x256x16), then G[(c,e)][(b,d)] = T[(b,c)][(d,e)].
__global__ void __launch_bounds__(256)
pair01_mma(const float* __restrict__ f0, const float* __restrict__ f1) {
    constexpr int ROWA = 24;    // halves per operand row (16 data + 8 pad) = 48 B
    constexpr int ROWT = 272;   // halves per T row (256 data + 16 pad)
    extern __shared__ fp16 sm1[];
    fp16* sA = sm1;                       // 256*24 halves
    fp16* sB = sm1 + 256 * ROWA;          // 256*24 halves
    fp16* sT = sm1 + 512 * ROWA;          // 256*272 halves
    const uint32_t uA = smem_u32(sA), uB = smem_u32(sB);
    const int tid = threadIdx.x, wid = tid >> 5, lane = tid & 31;
    const int ij = blockIdx.x, i = ij >> 5, j = ij & 31;

    // load + fp16 convert into K-major operand rows (row = (b,c) / (d,e), K=a)
    for (int p = tid; p < 4096; p += 256) {
        int a = p >> 8, r = p & 255;
        sA[r * ROWA + a] = __float2half(f0[i * 4096 + p]);           // f0[i,a,r]
        sB[r * ROWA + a] = __float2half(f1[a * 8192 + j * 256 + r]); // f1[a,j,r]
    }
    __syncthreads();

    // 8 warps: warp m-block = (wid>>1)*64; n side: (wid&1)*128, two 64-wide subtiles
    const int m0 = (wid >> 1) * 64;
    const int n0b = (wid & 1) * 128;

    uint32_t af[4][4];
    #pragma unroll
    for (int mi = 0; mi < 4; mi++) {
        uint32_t off = (uint32_t)(m0 + mi * 16 + (lane & 15)) * (ROWA * 2) +
                       (lane >> 4) * 16;
        ldsm4(af[mi][0], af[mi][1], af[mi][2], af[mi][3], uA + off);
    }

    #pragma unroll
    for (int nb = 0; nb < 2; nb++) {
        const int n0 = n0b + nb * 64;
        uint32_t bq[8][2];
        #pragma unroll
        for (int ni = 0; ni < 8; ni += 2) {
            uint32_t off = (uint32_t)(n0 + ni * 8 + ((lane >> 4) << 3) +
                                      (lane & 7)) * (ROWA * 2) +
                           ((lane >> 3) & 1) * 16;
            ldsm4(bq[ni][0], bq[ni][1], bq[ni + 1][0], bq[ni + 1][1], uB + off);
        }
        float acc[4][8][4];
        #pragma unroll
        for (int mi = 0; mi < 4; mi++)
            #pragma unroll
            for (int ni = 0; ni < 8; ni++) {
                #pragma unroll
                for (int c4 = 0; c4 < 4; c4++) acc[mi][ni][c4] = 0.f;
                mma16816(acc[mi][ni], af[mi], bq[ni]);
            }
        // stage into sT (natural (r, col) order, half2 stores)
        #pragma unroll
        for (int mi = 0; mi < 4; mi++)
            #pragma unroll
            for (int ni = 0; ni < 8; ni++) {
                int r   = m0 + mi * 16 + (lane >> 2);
                int col = n0 + ni * 8 + (lane & 3) * 2;
                #pragma unroll
                for (int h = 0; h < 2; h++) {
                    __half2 hv;
                    hv.x = __float2half(acc[mi][ni][h * 2]);
                    hv.y = __float2half(acc[mi][ni][h * 2 + 1]);
                    *reinterpret_cast<__half2*>(&sT[(r + h * 8) * ROWT + col]) = hv;
                }
            }
    }
    __syncthreads();

    // permuted copy-out: thread owns G row g=(c,e); (b,d) contiguous in output
    const int g = tid;
    const int c = g >> 4, e = g & 15;
    const long long gb = (long long)ij * 65536 + (long long)g * 256;
    #pragma unroll
    for (int v = 0; v < 32; v++) {
        int b = v >> 1, dbase = (v & 1) * 8;
        __align__(16) fp16 tmp[8];
        #pragma unroll
        for (int u = 0; u < 8; u++)
            tmp[u] = sT[(b * 16 + c) * ROWT + (dbase + u) * 16 + e];
        *reinterpret_cast<uint4*>(&g_G[gb + v * 8]) = *reinterpret_cast<uint4*>(tmp);
    }
}

// ------------------- fp16 single GEMM, BK=64 ---------------------------
// D[M,N] = A[M,K] * B[N,K]^T ; all K-major rows, lda/ldb leads.
// z-dim: B += z*sB, C += z*sC  (A has no batch).
// EPI: 0 -> fp16 out; 1 -> fp32 + bias.
template <int BM, int BN, int WM, int WN, int EPI>
__global__ void __launch_bounds__((BM / WM) * (BN / WN) * 32)
gemm_mma(const fp16* __restrict__ A, const fp16* __restrict__ B,
         float* __restrict__ Cf, fp16* __restrict__ Ch,
         const float* __restrict__ bias,
         int K, int lda, int ldb, int ldC,
         long long sB, long long sC) {
    constexpr int WARPS_M = BM / WM, WARPS_N = BN / WN;
    constexpr int THREADS = WARPS_M * WARPS_N * 32;
    constexpr int MT = WM / 16, NT = WN / 8;
    static_assert(NT % 2 == 0, "NT even for paired ldsm4");
    constexpr int ROWB = 144;                // 128B data + 16B pad (bank-safe)
    constexpr int A_SZ = BM * ROWB;
    constexpr int B_SZ = BN * ROWB;
    constexpr int BUFB = A_SZ + B_SZ;

    extern __shared__ char sm[];
    const uint32_t sbase = smem_u32(sm);
    const int tid = threadIdx.x, wid = tid >> 5, lane = tid & 31;
    const int warp_m0 = (wid / WARPS_N) * WM;
    const int warp_n0 = (wid % WARPS_N) * WN;

    const long long bz = blockIdx.z;
    B += bz * sB;
    const int m0 = blockIdx.y * BM;
    const int n0 = blockIdx.x * BN;

    float acc[MT][NT][4];
    #pragma unroll
    for (int mi = 0; mi < MT; mi++)
        #pragma unroll
        for (int ni = 0; ni < NT; ni++)
            #pragma unroll
            for (int c = 0; c < 4; c++) acc[mi][ni][c] = 0.f;

    auto load_chunk = [&](int kt, int buf) {
        const uint32_t sA = sbase + buf * BUFB;
        const uint32_t sBb = sA + A_SZ;
        #pragma unroll
        for (int p = tid; p < BM * 8; p += THREADS) {
            int row = p >> 3, u = p & 7;
            long long g = (long long)(m0 + row) * lda + kt + u * 8;
            cp16(sA + row * ROWB + u * 16, A + g);
        }
        #pragma unroll
        for (int p = tid; p < BN * 8; p += THREADS) {
            int row = p >> 3, u = p & 7;
            long long g = (long long)(n0 + row) * ldb + kt + u * 8;
            cp16(sBb + row * ROWB + u * 16, B + g);
        }
        cp_commit();
    };

    const int nch = K >> 6;   // BK = 64
    load_chunk(0, 0);
    cp_wait0();
    __syncthreads();

    for (int t = 0; t < nch; t++) {
        const int buf = t & 1;
        if (t + 1 < nch) load_chunk((t + 1) * 64, buf ^ 1);

        const uint32_t sA = sbase + buf * BUFB;
        const uint32_t sBb = sA + A_SZ;

        #pragma unroll
        for (int ks = 0; ks < 4; ks++) {
            uint32_t af[MT][4], bq[NT][2];
            #pragma unroll
            for (int mi = 0; mi < MT; mi++) {
                uint32_t off = (uint32_t)(warp_m0 + mi * 16 + (lane & 15)) * ROWB +
                               ks * 32 + (lane >> 4) * 16;
                ldsm4(af[mi][0], af[mi][1], af[mi][2], af[mi][3], sA + off);
            }
            #pragma unroll
            for (int ni = 0; ni < NT; ni += 2) {
                uint32_t off = (uint32_t)(warp_n0 + ni * 8 + ((lane >> 4) << 3) +
                                          (lane & 7)) * ROWB +
                               ks * 32 + ((lane >> 3) & 1) * 16;
                ldsm4(bq[ni][0], bq[ni][1], bq[ni + 1][0], bq[ni + 1][1], sBb + off);
            }
            #pragma unroll
            for (int mi = 0; mi < MT; mi++)
                #pragma unroll
                for (int ni = 0; ni < NT; ni++)
                    mma16816(acc[mi][ni], af[mi], bq[ni]);
        }
        cp_wait0();
        __syncthreads();
    }

    // epilogue: thread holds (r, col),(r, col+1),(r+8, col),(r+8, col+1)
    #pragma unroll
    for (int mi = 0; mi < MT; mi++) {
        #pragma unroll
        for (int ni = 0; ni < NT; ni++) {
            int r   = m0 + warp_m0 + mi * 16 + (lane >> 2);
            int col = n0 + warp_n0 + ni * 8 + (lane & 3) * 2;
            if (EPI == 0) {
                #pragma unroll
                for (int half_ = 0; half_ < 2; half_++) {
                    long long off = bz * sC + (long long)(r + half_ * 8) * ldC + col;
                    __half2 hv;
                    hv.x = __float2half(acc[mi][ni][half_ * 2]);
                    hv.y = __float2half(acc[mi][ni][half_ * 2 + 1]);
                    *reinterpret_cast<__half2*>(&Ch[off]) = hv;
                }
            } else {
                float b0 = bias[col], b1 = bias[col + 1];
                #pragma unroll
                for (int half_ = 0; half_ < 2; half_++) {
                    long long off = (long long)(r + half_ * 8) * ldC + col;
                    float2 v;
                    v.x = acc[mi][ni][half_ * 2]     + b0;
                    v.y = acc[mi][ni][half_ * 2 + 1] + b1;
                    *reinterpret_cast<float2*>(&Cf[off]) = v;
                }
            }
        }
    }
}

// -------- W[ij][kl] -> Wt[kl][ij], smem-tiled, coalesced both sides ----
__global__ void __launch_bounds__(256)
wtrans_kernel() {
    __shared__ fp16 tile[64][65];
    const int ij0 = blockIdx.x * 64;     // 16 blocks
    const int kl0 = blockIdx.y * 64;     // 64 blocks
    const int t = threadIdx.x;
    for (int idx = t; idx < 4096; idx += 256) {
        int r = idx >> 6, c = idx & 63;
        tile[r][c] = g_W[(long long)(ij0 + r) * 4096 + kl0 + c];
    }
    __syncthreads();
    for (int idx = t; idx < 4096; idx += 256) {
        int c = idx >> 6, r = idx & 63;
        g_Wt[(long long)(kl0 + c) * 1024 + ij0 + r] = tile[r][c];
    }
}

// ------------------- launch -------------------------------------------
extern "C" void kernel_launch(void* const* d_in, const int* in_sizes, int n_in,
                              void* d_out, int out_size) {
    const float* x    = (const float*)d_in[0];
    const float* f0   = (const float*)d_in[1];
    const float* f1   = (const float*)d_in[2];
    const float* f2   = (const float*)d_in[3];
    const float* f3   = (const float*)d_in[4];
    const float* bias = (const float*)d_in[5];
    float* out = (float*)d_out;

    fp16 *pF2, *pF3, *px, *pG, *pH, *pW, *pWt;
    cudaGetSymbolAddress((void**)&pF2, g_F2);
    cudaGetSymbolAddress((void**)&pF3, g_F3);
    cudaGetSymbolAddress((void**)&px,  g_x);
    cudaGetSymbolAddress((void**)&pG,  g_G);
    cudaGetSymbolAddress((void**)&pH,  g_H);
    cudaGetSymbolAddress((void**)&pW,  g_W);
    cudaGetSymbolAddress((void**)&pWt, g_Wt);

    // dynamic smem: 2 buffers of (A + B), ROWB=144 (BK=64)
    const int SMEM_128 = 2 * (128 * 144 + 128 * 144);   // 73728
    const int SMEM_S3  = 2 * (128 * 144 + 64 * 144);    // 55296
    const int SMEM_P01 = (512 * 24 + 256 * 272) * 2;    // 163840
    cudaFuncSetAttribute((const void*)gemm_mma<128, 128, 64, 64, 0>,
                         cudaFuncAttributeMaxDynamicSharedMemorySize, SMEM_128);
    cudaFuncSetAttribute((const void*)gemm_mma<128, 64, 64, 32, 0>,
                         cudaFuncAttributeMaxDynamicSharedMemorySize, SMEM_S3);
    cudaFuncSetAttribute((const void*)gemm_mma<128, 128, 64, 64, 1>,
                         cudaFuncAttributeMaxDynamicSharedMemorySize, SMEM_128);
    cudaFuncSetAttribute((const void*)pair01_mma,
                         cudaFuncAttributeMaxDynamicSharedMemorySize, SMEM_P01);

    prep_tables<<<1024, 256>>>(f2, f3);
    prep_x<<<8192, 256>>>(x);            // 4 elems/thread (float4 -> half2x2)

    // stage 1: G[ij][ce][bd] fp16 via tensor cores + permute
    pair01_mma<<<1024, 256, SMEM_P01>>>(f0, f1);

    // stage 2: per-ij H[kf=1024][ce=256] = F2 . G_ij^T   (K=256)
    gemm_mma<128, 128, 64, 64, 0><<<dim3(2, 8, 1024), 128, SMEM_128>>>(
        pF2, pG,
        nullptr, pH, nullptr,
        /*K=*/256, /*lda=*/256, /*ldb=*/256, /*ldC=*/256,
        /*sB=*/65536LL, /*sC=*/262144LL);

    // stage 3: W[(ij,k)=65536][l=64] = H . F3^T          (K=4096)
    //          flat offset = ij*4096 + kl  -> W[ij][kl] row-major
    gemm_mma<128, 64, 64, 32, 0><<<dim3(1, 512, 1), 128, SMEM_S3>>>(
        pH, pF3,
        nullptr, pW, nullptr,
        /*K=*/4096, /*lda=*/4096, /*ldb=*/4096, /*ldC=*/64,
        /*sB=*/0, /*sC=*/0);

    // transpose -> Wt[kl][ij] fp16 (coalesced both sides)
    wtrans_kernel<<<dim3(16, 64), 256>>>();

    // stage 4: out[8192][4096] = x . Wt^T + bias         (K=1024)
    gemm_mma<128, 128, 64, 64, 1><<<dim3(32, 64, 1), 128, SMEM_128>>>(
        px, pWt,
        out, nullptr, bias,
        /*K=*/1024, /*lda=*/1024, /*ldb=*/1024, /*ldC=*/4096,
        0, 0);
}

// round 17
// speedup vs baseline: 1.1526x; 1.0071x over previous
#include <cuda_runtime.h>
#include <cuda_fp16.h>
#include <cstdint>

// =====================================================================
// Tree (121 GMAC):
//  G[ij][ce][bd]  = sum_a f0[i,a,b,c] f1[a,j,d,e]      (mma, per-ij 256x256x16)
//  H[ij][kf][ce]  = F2[kf,bd] . G[ce,bd]^T             (1-MMA, batched, cs-store)
//  W[(ij,k)][l]   = H[(ij,k),(f,ce)] . F3[l,(f,ce)]^T  (1-MMA, coalesced out)
//  out[z][kl]     = x[z,ij] . Wt[kl,ij]^T + bias       (1-MMA, cs-store)
//
// All operands single fp16, fp32 accumulate (rel_err 5.85e-4, measured).
// GEMM core at the single-MMA plateau (~277 TF issued; density register-
// capped at 64x64 warp tile / 168 regs / 3 CTA/SM). This round: streaming
// (__stcs, evict-first) stores for the two write-once streams H (512 MB)
// and out (134 MB) to stop them evicting the L2-reused G/F2/Wt lines
// (stage-2 L2 53% busy vs DRAM 15%). Arithmetic unchanged.
// =====================================================================

typedef __half fp16;

// ------------------- scratch (device globals) ------------------------
__device__ __align__(256) fp16  g_F2[1024 * 256];
__device__ __align__(256) fp16  g_F3[64 * 4096];
__device__ __align__(256) fp16  g_x[8192 * 1024];
__device__ __align__(256) fp16  g_G[1024LL * 256 * 256];     // 128 MB
__device__ __align__(256) fp16  g_H[1024LL * 1024 * 256];    // 512 MB
__device__ __align__(256) fp16  g_W[1024LL * 4096];          // 8 MB  [ij][kl]
__device__ __align__(256) fp16  g_Wt[4096 * 1024];           // 8 MB  [kl][ij]

// ------------------- helpers ------------------------------------------
__device__ __forceinline__ uint32_t smem_u32(const void* p) {
    uint32_t a;
    asm("{ .reg .u64 t; cvta.to.shared.u64 t, %1; cvt.u32.u64 %0, t; }"
        : "=r"(a) : "l"(p));
    return a;
}
__device__ __forceinline__ void cp16(uint32_t s, const void* g) {
    asm volatile("cp.async.cg.shared.global [%0], [%1], 16;" :: "r"(s), "l"(g));
}
__device__ __forceinline__ void cp_commit() {
    asm volatile("cp.async.commit_group;" ::: "memory");
}
__device__ __forceinline__ void cp_wait0() {
    asm volatile("cp.async.wait_group 0;" ::: "memory");
}
__device__ __forceinline__ void ldsm4(uint32_t& r0, uint32_t& r1,
                                      uint32_t& r2, uint32_t& r3, uint32_t addr) {
    asm volatile("ldmatrix.sync.aligned.m8n8.x4.shared.b16 {%0,%1,%2,%3}, [%4];"
                 : "=r"(r0), "=r"(r1), "=r"(r2), "=r"(r3) : "r"(addr));
}
__device__ __forceinline__ void mma16816(float (&d)[4], const uint32_t (&a)[4],
                                         const uint32_t (&b)[2]) {
    asm volatile(
        "mma.sync.aligned.m16n8k16.row.col.f32.f16.f16.f32 "
        "{%0,%1,%2,%3}, {%4,%5,%6,%7}, {%8,%9}, {%0,%1,%2,%3};"
        : "+f"(d[0]), "+f"(d[1]), "+f"(d[2]), "+f"(d[3])
        : "r"(a[0]), "r"(a[1]), "r"(a[2]), "r"(a[3]), "r"(b[0]), "r"(b[1]));
}

// ------------------- prep: tables + x --------------------------------
__global__ void prep_tables(const float* __restrict__ f2,
                            const float* __restrict__ f3) {
    int o = blockIdx.x * 256 + threadIdx.x;          // 0 .. 262143
    // F2t[kf][bd] = f2[(bd)*1024 + kf]
    g_F2[o] = __float2half(f2[(o & 255) * 1024 + (o >> 8)]);
    // F3T[l][f*256 + c*16 + e] = f3[((c*16+e)*16+f)*64 + l]
    int l = o >> 12, fce = o & 4095, f = fce >> 8, ce = fce & 255;
    g_F3[o] = __float2half(f3[(ce * 16 + f) * 64 + l]);
}
// vectorized x conversion: 4 floats -> 4 halves per thread
__global__ void prep_x(const float* __restrict__ x) {
    int o = blockIdx.x * 256 + threadIdx.x;          // 0 .. 2097151
    float4 v = reinterpret_cast<const float4*>(x)[o];
    __half2 h0 = __floats2half2_rn(v.x, v.y);
    __half2 h1 = __floats2half2_rn(v.z, v.w);
    uint2 pk;
    pk.x = *reinterpret_cast<uint32_t*>(&h0);
    pk.y = *reinterpret_cast<uint32_t*>(&h1);
    reinterpret_cast<uint2*>(g_x)[o] = pk;
}

// ------------- stage 1 (tensor): T = A.B^T then permute ----------------
// Per CTA (one ij): T[(b,c)][(d,e)] = sum_a f0[i,a,b,c]*f1[a,j,d,e]
// (GEMM 256x256x16), then G[(c,e)][(b,d)] = T[(b,c)][(d,e)].
__global__ void __launch_bounds__(256)
pair01_mma(const float* __restrict__ f0, const float* __restrict__ f1) {
    constexpr int ROWA = 24;    // halves per operand row (16 data + 8 pad) = 48 B
    constexpr int ROWT = 272;   // halves per T row (256 data + 16 pad)
    extern __shared__ fp16 sm1[];
    fp16* sA = sm1;                       // 256*24 halves
    fp16* sB = sm1 + 256 * ROWA;          // 256*24 halves
    fp16* sT = sm1 + 512 * ROWA;          // 256*272 halves
    const uint32_t uA = smem_u32(sA), uB = smem_u32(sB);
    const int tid = threadIdx.x, wid = tid >> 5, lane = tid & 31;
    const int ij = blockIdx.x, i = ij >> 5, j = ij & 31;

    // load + fp16 convert into K-major operand rows (row = (b,c) / (d,e), K=a)
    for (int p = tid; p < 4096; p += 256) {
        int a = p >> 8, r = p & 255;
        sA[r * ROWA + a] = __float2half(f0[i * 4096 + p]);           // f0[i,a,r]
        sB[r * ROWA + a] = __float2half(f1[a * 8192 + j * 256 + r]); // f1[a,j,r]
    }
    __syncthreads();

    // 8 warps: warp m-block = (wid>>1)*64; n side: (wid&1)*128, two 64-wide subtiles
    const int m0 = (wid >> 1) * 64;
    const int n0b = (wid & 1) * 128;

    uint32_t af[4][4];
    #pragma unroll
    for (int mi = 0; mi < 4; mi++) {
        uint32_t off = (uint32_t)(m0 + mi * 16 + (lane & 15)) * (ROWA * 2) +
                       (lane >> 4) * 16;
        ldsm4(af[mi][0], af[mi][1], af[mi][2], af[mi][3], uA + off);
    }

    #pragma unroll
    for (int nb = 0; nb < 2; nb++) {
        const int n0 = n0b + nb * 64;
        uint32_t bq[8][2];
        #pragma unroll
        for (int ni = 0; ni < 8; ni += 2) {
            uint32_t off = (uint32_t)(n0 + ni * 8 + ((lane >> 4) << 3) +
                                      (lane & 7)) * (ROWA * 2) +
                           ((lane >> 3) & 1) * 16;
            ldsm4(bq[ni][0], bq[ni][1], bq[ni + 1][0], bq[ni + 1][1], uB + off);
        }
        float acc[4][8][4];
        #pragma unroll
        for (int mi = 0; mi < 4; mi++)
            #pragma unroll
            for (int ni = 0; ni < 8; ni++) {
                #pragma unroll
                for (int c4 = 0; c4 < 4; c4++) acc[mi][ni][c4] = 0.f;
                mma16816(acc[mi][ni], af[mi], bq[ni]);
            }
        // stage into sT (natural (r, col) order, half2 stores)
        #pragma unroll
        for (int mi = 0; mi < 4; mi++)
            #pragma unroll
            for (int ni = 0; ni < 8; ni++) {
                int r   = m0 + mi * 16 + (lane >> 2);
                int col = n0 + ni * 8 + (lane & 3) * 2;
                #pragma unroll
                for (int h = 0; h < 2; h++) {
                    __half2 hv;
                    hv.x = __float2half(acc[mi][ni][h * 2]);
                    hv.y = __float2half(acc[mi][ni][h * 2 + 1]);
                    *reinterpret_cast<__half2*>(&sT[(r + h * 8) * ROWT + col]) = hv;
                }
            }
    }
    __syncthreads();

    // permuted copy-out: thread owns G row g=(c,e); (b,d) contiguous in output
    const int g = tid;
    const int c = g >> 4, e = g & 15;
    const long long gb = (long long)ij * 65536 + (long long)g * 256;
    #pragma unroll
    for (int v = 0; v < 32; v++) {
        int b = v >> 1, dbase = (v & 1) * 8;
        __align__(16) fp16 tmp[8];
        #pragma unroll
        for (int u = 0; u < 8; u++)
            tmp[u] = sT[(b * 16 + c) * ROWT + (dbase + u) * 16 + e];
        *reinterpret_cast<uint4*>(&g_G[gb + v * 8]) = *reinterpret_cast<uint4*>(tmp);
    }
}

// ------------------- fp16 single GEMM, BK=64 ---------------------------
// D[M,N] = A[M,K] * B[N,K]^T ; all K-major rows, lda/ldb leads.
// z-dim: B += z*sB, C += z*sC  (A has no batch).
// EPI: 0 -> fp16 out; 1 -> fp32 + bias (streaming); 3 -> fp16 streaming.
template <int BM, int BN, int WM, int WN, int EPI>
__global__ void __launch_bounds__((BM / WM) * (BN / WN) * 32)
gemm_mma(const fp16* __restrict__ A, const fp16* __restrict__ B,
         float* __restrict__ Cf, fp16* __restrict__ Ch,
         const float* __restrict__ bias,
         int K, int lda, int ldb, int ldC,
         long long sB, long long sC) {
    constexpr int WARPS_M = BM / WM, WARPS_N = BN / WN;
    constexpr int THREADS = WARPS_M * WARPS_N * 32;
    constexpr int MT = WM / 16, NT = WN / 8;
    static_assert(NT % 2 == 0, "NT even for paired ldsm4");
    constexpr int ROWB = 144;                // 128B data + 16B pad (bank-safe)
    constexpr int A_SZ = BM * ROWB;
    constexpr int B_SZ = BN * ROWB;
    constexpr int BUFB = A_SZ + B_SZ;

    extern __shared__ char sm[];
    const uint32_t sbase = smem_u32(sm);
    const int tid = threadIdx.x, wid = tid >> 5, lane = tid & 31;
    const int warp_m0 = (wid / WARPS_N) * WM;
    const int warp_n0 = (wid % WARPS_N) * WN;

    const long long bz = blockIdx.z;
    B += bz * sB;
    const int m0 = blockIdx.y * BM;
    const int n0 = blockIdx.x * BN;

    float acc[MT][NT][4];
    #pragma unroll
    for (int mi = 0; mi < MT; mi++)
        #pragma unroll
        for (int ni = 0; ni < NT; ni++)
            #pragma unroll
            for (int c = 0; c < 4; c++) acc[mi][ni][c] = 0.f;

    auto load_chunk = [&](int kt, int buf) {
        const uint32_t sA = sbase + buf * BUFB;
        const uint32_t sBb = sA + A_SZ;
        #pragma unroll
        for (int p = tid; p < BM * 8; p += THREADS) {
            int row = p >> 3, u = p & 7;
            long long g = (long long)(m0 + row) * lda + kt + u * 8;
            cp16(sA + row * ROWB + u * 16, A + g);
        }
        #pragma unroll
        for (int p = tid; p < BN * 8; p += THREADS) {
            int row = p >> 3, u = p & 7;
            long long g = (long long)(n0 + row) * ldb + kt + u * 8;
            cp16(sBb + row * ROWB + u * 16, B + g);
        }
        cp_commit();
    };

    const int nch = K >> 6;   // BK = 64
    load_chunk(0, 0);
    cp_wait0();
    __syncthreads();

    for (int t = 0; t < nch; t++) {
        const int buf = t & 1;
        if (t + 1 < nch) load_chunk((t + 1) * 64, buf ^ 1);

        const uint32_t sA = sbase + buf * BUFB;
        const uint32_t sBb = sA + A_SZ;

        #pragma unroll
        for (int ks = 0; ks < 4; ks++) {
            uint32_t af[MT][4], bq[NT][2];
            #pragma unroll
            for (int mi = 0; mi < MT; mi++) {
                uint32_t off = (uint32_t)(warp_m0 + mi * 16 + (lane & 15)) * ROWB +
                               ks * 32 + (lane >> 4) * 16;
                ldsm4(af[mi][0], af[mi][1], af[mi][2], af[mi][3], sA + off);
            }
            #pragma unroll
            for (int ni = 0; ni < NT; ni += 2) {
                uint32_t off = (uint32_t)(warp_n0 + ni * 8 + ((lane >> 4) << 3) +
                                          (lane & 7)) * ROWB +
                               ks * 32 + ((lane >> 3) & 1) * 16;
                ldsm4(bq[ni][0], bq[ni][1], bq[ni + 1][0], bq[ni + 1][1], sBb + off);
            }
            #pragma unroll
            for (int mi = 0; mi < MT; mi++)
                #pragma unroll
                for (int ni = 0; ni < NT; ni++)
                    mma16816(acc[mi][ni], af[mi], bq[ni]);
        }
        cp_wait0();
        __syncthreads();
    }

    // epilogue: thread holds (r, col),(r, col+1),(r+8, col),(r+8, col+1)
    #pragma unroll
    for (int mi = 0; mi < MT; mi++) {
        #pragma unroll
        for (int ni = 0; ni < NT; ni++) {
            int r   = m0 + warp_m0 + mi * 16 + (lane >> 2);
            int col = n0 + warp_n0 + ni * 8 + (lane & 3) * 2;
            if (EPI == 0 || EPI == 3) {
                #pragma unroll
                for (int half_ = 0; half_ < 2; half_++) {
                    long long off = bz * sC + (long long)(r + half_ * 8) * ldC + col;
                    __half2 hv;
                    hv.x = __float2half(acc[mi][ni][half_ * 2]);
                    hv.y = __float2half(acc[mi][ni][half_ * 2 + 1]);
                    if (EPI == 3)
                        __stcs(reinterpret_cast<__half2*>(&Ch[off]), hv);
                    else
                        *reinterpret_cast<__half2*>(&Ch[off]) = hv;
                }
            } else {
                float b0 = bias[col], b1 = bias[col + 1];
                #pragma unroll
                for (int half_ = 0; half_ < 2; half_++) {
                    long long off = (long long)(r + half_ * 8) * ldC + col;
                    float2 v;
                    v.x = acc[mi][ni][half_ * 2]     + b0;
                    v.y = acc[mi][ni][half_ * 2 + 1] + b1;
                    __stcs(reinterpret_cast<float2*>(&Cf[off]), v);
                }
            }
        }
    }
}

// -------- W[ij][kl] -> Wt[kl][ij], smem-tiled, coalesced both sides ----
__global__ void __launch_bounds__(256)
wtrans_kernel() {
    __shared__ fp16 tile[64][65];
    const int ij0 = blockIdx.x * 64;     // 16 blocks
    const int kl0 = blockIdx.y * 64;     // 64 blocks
    const int t = threadIdx.x;
    for (int idx = t; idx < 4096; idx += 256) {
        int r = idx >> 6, c = idx & 63;
        tile[r][c] = g_W[(long long)(ij0 + r) * 4096 + kl0 + c];
    }
    __syncthreads();
    for (int idx = t; idx < 4096; idx += 256) {
        int c = idx >> 6, r = idx & 63;
        g_Wt[(long long)(kl0 + c) * 1024 + ij0 + r] = tile[r][c];
    }
}

// ------------------- launch -------------------------------------------
extern "C" void kernel_launch(void* const* d_in, const int* in_sizes, int n_in,
                              void* d_out, int out_size) {
    const float* x    = (const float*)d_in[0];
    const float* f0   = (const float*)d_in[1];
    const float* f1   = (const float*)d_in[2];
    const float* f2   = (const float*)d_in[3];
    const float* f3   = (const float*)d_in[4];
    const float* bias = (const float*)d_in[5];
    float* out = (float*)d_out;

    fp16 *pF2, *pF3, *px, *pG, *pH, *pW, *pWt;
    cudaGetSymbolAddress((void**)&pF2, g_F2);
    cudaGetSymbolAddress((void**)&pF3, g_F3);
    cudaGetSymbolAddress((void**)&px,  g_x);
    cudaGetSymbolAddress((void**)&pG,  g_G);
    cudaGetSymbolAddress((void**)&pH,  g_H);
    cudaGetSymbolAddress((void**)&pW,  g_W);
    cudaGetSymbolAddress((void**)&pWt, g_Wt);

    // dynamic smem: 2 buffers of (A + B), ROWB=144 (BK=64)
    const int SMEM_128 = 2 * (128 * 144 + 128 * 144);   // 73728
    const int SMEM_S3  = 2 * (128 * 144 + 64 * 144);    // 55296
    const int SMEM_P01 = (512 * 24 + 256 * 272) * 2;    // 163840
    cudaFuncSetAttribute((const void*)gemm_mma<128, 128, 64, 64, 3>,
                         cudaFuncAttributeMaxDynamicSharedMemorySize, SMEM_128);
    cudaFuncSetAttribute((const void*)gemm_mma<128, 64, 64, 32, 0>,
                         cudaFuncAttributeMaxDynamicSharedMemorySize, SMEM_S3);
    cudaFuncSetAttribute((const void*)gemm_mma<128, 128, 64, 64, 1>,
                         cudaFuncAttributeMaxDynamicSharedMemorySize, SMEM_128);
    cudaFuncSetAttribute((const void*)pair01_mma,
                         cudaFuncAttributeMaxDynamicSharedMemorySize, SMEM_P01);

    prep_tables<<<1024, 256>>>(f2, f3);
    prep_x<<<8192, 256>>>(x);            // 4 elems/thread (float4 -> half2x2)

    // stage 1: G[ij][ce][bd] fp16 via tensor cores + permute
    pair01_mma<<<1024, 256, SMEM_P01>>>(f0, f1);

    // stage 2: per-ij H[kf=1024][ce=256] = F2 . G_ij^T   (K=256)
    //          H is write-once/read-much-later -> streaming stores (EPI=3)
    gemm_mma<128, 128, 64, 64, 3><<<dim3(2, 8, 1024), 128, SMEM_128>>>(
        pF2, pG,
        nullptr, pH, nullptr,
        /*K=*/256, /*lda=*/256, /*ldb=*/256, /*ldC=*/256,
        /*sB=*/65536LL, /*sC=*/262144LL);

    // stage 3: W[(ij,k)=65536][l=64] = H . F3^T          (K=4096)
    //          flat offset = ij*4096 + kl  -> W[ij][kl] row-major
    //          W is re-read immediately (wtrans) -> normal stores (EPI=0)
    gemm_mma<128, 64, 64, 32, 0><<<dim3(1, 512, 1), 128, SMEM_S3>>>(
        pH, pF3,
        nullptr, pW, nullptr,
        /*K=*/4096, /*lda=*/4096, /*ldb=*/4096, /*ldC=*/64,
        /*sB=*/0, /*sC=*/0);

    // transpose -> Wt[kl][ij] fp16 (coalesced both sides)
    wtrans_kernel<<<dim3(16, 64), 256>>>();

    // stage 4: out[8192][4096] = x . Wt^T + bias         (K=1024)
    //          out is never re-read -> streaming fp32 stores (EPI=1)
    gemm_mma<128, 128, 64, 64, 1><<<dim3(32, 64, 1), 128, SMEM_128>>>(
        px, pWt,
        out, nullptr, bias,
        /*K=*/1024, /*lda=*/1024, /*ldb=*/1024, /*ldC=*/4096,
        0, 0);
}